// round 14
// baseline (speedup 1.0000x reference)
#include <cuda_runtime.h>
#include <math.h>

#define A_DIM 20
#define L_DIM 512
#define CH 8
#define B_DIM 1024
#define TPB 128   // 4 warps; warp w owns amino acids 5w..5w+4

__device__ float g_Wt[L_DIM * CH];     // transposed: [l*8 + c]
__device__ float g_Vt[A_DIM * 21];     // Vt[a*21+s] = V[s][a] + (s==a); s=20 -> 0
__device__ float g_vk[3];              // v1, v2, v3
__device__ int   g_flag;               // monotonic build-done counter

// ---------------------------------------------------------------------------
// f32x2 packed helpers
// ---------------------------------------------------------------------------
__device__ __forceinline__ unsigned long long pack2(float lo, float hi) {
    unsigned long long r;
    asm("mov.b64 %0, {%1, %2};" : "=l"(r) : "f"(lo), "f"(hi));
    return r;
}
__device__ __forceinline__ void unpack2(unsigned long long v, float& lo, float& hi) {
    asm("mov.b64 {%0, %1}, %2;" : "=f"(lo), "=f"(hi) : "l"(v));
}
__device__ __forceinline__ void ffma2(unsigned long long& d, unsigned long long a,
                                      unsigned long long b) {
    asm("fma.rn.f32x2 %0, %1, %2, %0;" : "+l"(d) : "l"(a), "l"(b));
}
__device__ __forceinline__ unsigned long long add2(unsigned long long a,
                                                   unsigned long long b) {
    unsigned long long r;
    asm("add.rn.f32x2 %0, %1, %2;" : "=l"(r) : "l"(a), "l"(b));
    return r;
}

// ---------------------------------------------------------------------------
// Fused kernel. One block per batch element.
// Blocks 0..7 additionally build W channel oc=blockIdx (block 0 also Vt/vk).
// smem overlay: build buffers reuse the Wt/scm/sc1s region (disjoint in time).
// ---------------------------------------------------------------------------
__global__ __launch_bounds__(TPB, 7) void fused_kernel(const float* __restrict__ x,
                                                       const float* __restrict__ lpm,
                                                       const float* __restrict__ pm,
                                                       const float* __restrict__ stdv,
                                                       const float* __restrict__ w0,
                                                       const float* __restrict__ ws,
                                                       float* __restrict__ out) {
    __shared__ __align__(16) unsigned char ov[22528];
    __shared__ float Vt[A_DIM * 21];
    __shared__ int   sav[L_DIM];
    __shared__ int   sWmax[4];
    __shared__ float sw0s[CH * 3];

    // main-phase views of the overlay
    float*              WtS  = (float*)ov;                          // 16 KB [l*8+c]
    unsigned long long* scm  = (unsigned long long*)(ov + 16384);   // 4 KB  (c2<<32)|c3
    unsigned*           sc1s = (unsigned*)(ov + 20480);             // 2 KB  c1 | (s<<24)

    int tid = threadIdx.x, b = blockIdx.x;
    int warp = tid >> 5, lane = tid & 31;

    // --- Phase A: decode one-hot via weighted-sum FMA (LDG burst first) ---
    const float* xb = x + (size_t)b * (L_DIM * A_DIM);
    int lmax = -1;
    #pragma unroll
    for (int r = 0; r < 4; r++) {
        int l = tid + r * TPB;
        const float4* p = (const float4*)(xb + l * A_DIM);
        float4 q0 = p[0], q1 = p[1], q2 = p[2], q3 = p[3], q4 = p[4];
        float a0 = fmaf(q0.x, 1.f, fmaf(q0.y, 2.f, fmaf(q0.z, 3.f, q0.w * 4.f)));
        float a1 = fmaf(q1.x, 5.f, fmaf(q1.y, 6.f, fmaf(q1.z, 7.f, q1.w * 8.f)));
        float a2 = fmaf(q2.x, 9.f, fmaf(q2.y, 10.f, fmaf(q2.z, 11.f, q2.w * 12.f)));
        float a3 = fmaf(q3.x, 13.f, fmaf(q3.y, 14.f, fmaf(q3.z, 15.f, q3.w * 16.f)));
        float a4 = fmaf(q4.x, 17.f, fmaf(q4.y, 18.f, fmaf(q4.z, 19.f, q4.w * 20.f)));
        float fa = ((a0 + a1) + (a2 + a3)) + a4;
        int v = (int)fa;                  // exact: small ints
        sav[l] = (v == 0) ? 20 : v - 1;
        if (v != 0) lmax = l;
    }
    lmax = __reduce_max_sync(0xFFFFFFFFu, lmax);
    if (lane == 0) sWmax[warp] = lmax;

    // --- W builder (blocks 0..7): adjoint composition into g_Wt ---
    if (b < CH) {
        if (b == 0) {
            for (int i = tid; i < A_DIM * 21; i += TPB) {
                int a = i / 21, s = i % 21;
                float v = (s == a) ? 1.f : 0.f;
                if (s < A_DIM) {
                    if (a > s && a <= A_DIM - 2)
                        v += fminf(fmaxf(lpm[s * A_DIM + a], 0.001f), 1.f) * pm[s * A_DIM + a];
                    if (a < s)
                        v += fminf(fmaxf(lpm[a * A_DIM + s], 0.001f), 1.f) * pm[a * A_DIM + s];
                }
                g_Vt[i] = v;
            }
            if (tid < 3) {
                float s0 = stdv[0];
                float k = (float)(tid + 1);
                g_vk[tid] = expf(-(k * k) / (2.f * s0 * s0));
            }
        }
        // overlay build views (free until WtS/scm/sc1s are used)
        float* buf0 = (float*)ov;             // stride 256, 8 KB
        float* buf1 = (float*)(ov + 8192);    // stride 128, 4 KB
        float* sws  = (float*)(ov + 12288);   // 1536 floats, 6 KB

        for (int i = tid; i < 8 * CH * CH * 3; i += TPB) sws[i] = ws[i];
        if (tid < CH * 3) sw0s[tid] = w0[tid];
        if (tid < CH) buf0[tid * 256] = (tid == b) ? 1.f : 0.f;
        __syncthreads();

        float* cur = buf0; int curs = 256;
        for (int j = 7; j >= 0; j--) {
            int sh = 8 - j;                    // L2h = 1 << sh
            int L2h = 1 << sh;
            float* dst = (j & 1) ? buf1 : buf0;
            int dsts = (j & 1) ? 128 : 256;
            const float* w = sws + j * (CH * CH * 3);
            for (int e = tid; e < CH * L2h; e += TPB) {
                int ci = e >> sh, q = e & (L2h - 1);
                float acc = 0.f;
                #pragma unroll
                for (int co = 0; co < CH; co++) {
                    const float* wc = w + (co * CH + ci) * 3;
                    #pragma unroll
                    for (int t = 0; t < 3; t++) {
                        int p = q + 1 - t;
                        if (p >= 0 && p < L2h) acc += wc[t] * 0.5f * cur[co * curs + (p >> 1)];
                    }
                }
                dst[ci * dsts + q] = acc;
            }
            __syncthreads();
            cur = dst; curs = dsts;
        }
        // final backward through pool0+conv0: cur = buf0 (CH x 256)
        for (int q = tid; q < 512; q += TPB) {
            float acc = 0.f;
            #pragma unroll
            for (int co = 0; co < CH; co++) {
                #pragma unroll
                for (int t = 0; t < 3; t++) {
                    int p = q + 1 - t;
                    if (p >= 0 && p < 512) acc += sw0s[co * 3 + t] * 0.5f * cur[co * 256 + (p >> 1)];
                }
            }
            g_Wt[q * CH + b] = acc;
        }
        __threadfence();
        __syncthreads();
        if (tid == 0) atomicAdd(&g_flag, 1);
    }
    __syncthreads();   // sav/sWmax ready; builders done with overlay

    int Lmax = max(max(sWmax[0], sWmax[1]), max(sWmax[2], sWmax[3]));
    int NB = min(L_DIM, (Lmax + 4 + 31) & ~31);   // positions >= NB contribute 0

    // --- Phase B: exclusive class masks (independent of W -> before spin) ---
    for (int l = tid; l < NB; l += TPB) {
        unsigned c1, c2, c3;
        if (l == 0) {
            c3 = (1u << sav[0]) | (1u << sav[1]) | (1u << sav[2]) | (1u << sav[3]);
            c2 = 0u; c1 = 0u;
        } else if (l == L_DIM - 1) {
            c3 = (1u << sav[511]) | (1u << sav[510]) | (1u << sav[509]) | (1u << sav[508]);
            c2 = 0u; c1 = 0u;
        } else {
            unsigned m1 = (1u << sav[l - 1]) | (1u << sav[l + 1]);
            unsigned m2 = ((l >= 2) ? (1u << sav[l - 2]) : 0u) |
                          ((l <= 509) ? (1u << sav[l + 2]) : 0u);
            unsigned m3 = ((l >= 3) ? (1u << sav[l - 3]) : 0u) |
                          ((l <= 508) ? (1u << sav[l + 3]) : 0u);
            c3 = m3;
            c2 = m2 & ~m3;
            c1 = m1 & ~(m2 | m3);
        }
        scm[l]  = ((unsigned long long)c2 << 32) | c3;
        sc1s[l] = (c1 & 0x1FFFFFu) | ((unsigned)sav[l] << 24);
    }

    // --- rendezvous: wait until all 8 W channels (+Vt/vk) are published ---
    if (tid == 0) {
        while (atomicAdd(&g_flag, 0) < CH) __nanosleep(64);
    }
    __syncthreads();
    __threadfence();   // acquire: order subsequent g_Wt/g_Vt reads

    // --- copy block-invariant tables (straight vector copies) ---
    {
        const float4* srcW = (const float4*)g_Wt;   // 4096 floats = 1024 float4
        float4* dstW = (float4*)WtS;
        #pragma unroll
        for (int r = 0; r < 8; r++) dstW[tid + r * TPB] = srcW[tid + r * TPB];
        const float4* srcV = (const float4*)g_Vt;   // 420 floats = 105 float4
        float4* dstV = (float4*)Vt;
        if (tid < 105) dstV[tid] = srcV[tid];
    }
    float v1 = g_vk[0], v2 = g_vk[1], v3 = g_vk[2];
    __syncthreads();

    int abase = warp * 5;
    unsigned long long acc[5][4];
    #pragma unroll
    for (int aa = 0; aa < 5; aa++)
        #pragma unroll
        for (int j = 0; j < 4; j++) acc[aa][j] = 0ull;

    unsigned abit[5]; int vb[5];
    #pragma unroll
    for (int aa = 0; aa < 5; aa++) {
        abit[aa] = 1u << (abase + aa);
        vb[aa] = (abase + aa) * 21;
    }

    // --- Phase C: bounded, barrier-free packed accumulation ---
    int NI = NB >> 5;
    #pragma unroll 2
    for (int i = 0; i < NI; i++) {
        int l = lane + 32 * i;
        unsigned long long m = scm[l];
        unsigned c3m = (unsigned)m;
        unsigned c2m = (unsigned)(m >> 32);
        unsigned t = sc1s[l];
        unsigned c1m = t & 0x1FFFFFu;
        int s = (int)(t >> 24);
        const ulonglong2* wl = (const ulonglong2*)(WtS + l * 8);
        ulonglong2 w01 = wl[0];           // LDS.128: channels 0-3
        ulonglong2 w23 = wl[1];           // LDS.128: channels 4-7
        #pragma unroll
        for (int aa = 0; aa < 5; aa++) {
            float rv = (c3m & abit[aa]) ? v3
                     : (c2m & abit[aa]) ? v2
                     : (c1m & abit[aa]) ? v1 : 0.f;
            float h = rv + Vt[vb[aa] + s];
            unsigned long long hh = pack2(h, h);
            ffma2(acc[aa][0], w01.x, hh);
            ffma2(acc[aa][1], w01.y, hh);
            ffma2(acc[aa][2], w23.x, hh);
            ffma2(acc[aa][3], w23.y, hh);
        }
    }

    // --- Phase D: native u64 butterfly (2 SHFL + 1 FADD2 per step) ---
    #pragma unroll
    for (int aa = 0; aa < 5; aa++) {
        #pragma unroll
        for (int j = 0; j < 4; j++) {
            unsigned long long v = acc[aa][j];
            #pragma unroll
            for (int off = 16; off; off >>= 1)
                v = add2(v, __shfl_xor_sync(0xFFFFFFFFu, v, off));
            acc[aa][j] = v;
        }
        if (lane == 0) {
            float r[8];
            #pragma unroll
            for (int j = 0; j < 4; j++) unpack2(acc[aa][j], r[2 * j], r[2 * j + 1]);
            float4* o = (float4*)(out + (size_t)b * (A_DIM * CH) + (abase + aa) * CH);
            o[0] = make_float4(r[0], r[1], r[2], r[3]);
            o[1] = make_float4(r[4], r[5], r[6], r[7]);
        }
    }
}

// ---------------------------------------------------------------------------
// Inputs (metadata order): x, masks(unused), lpm, pm, std, w0, ws
// Output: float32 (B, A, CH) = (1024, 20, 8)
// ---------------------------------------------------------------------------
extern "C" void kernel_launch(void* const* d_in, const int* in_sizes, int n_in,
                              void* d_out, int out_size) {
    const float* x    = (const float*)d_in[0];
    const float* lpm  = (const float*)d_in[2];
    const float* pm   = (const float*)d_in[3];
    const float* stdv = (const float*)d_in[4];
    const float* w0   = (const float*)d_in[5];
    const float* ws   = (const float*)d_in[6];
    float* out = (float*)d_out;

    fused_kernel<<<B_DIM, TPB>>>(x, lpm, pm, stdv, w0, ws, out);
}

// round 15
// speedup vs baseline: 1.0556x; 1.0556x over previous
#include <cuda_runtime.h>
#include <math.h>

#define A_DIM 20
#define L_DIM 512
#define CH 8
#define B_DIM 1024
#define TPB 128   // 4 warps; warp w owns amino acids 5w..5w+4

__device__ float g_Wf[4 * L_DIM * 2];  // interleaved channel pairs: [j*1024 + 2l + parity]
__device__ float g_Vt[A_DIM * 21];     // Vt[a*21+s] = V[s][a] + (s==a); s=20 -> 0
__device__ float g_vk[3];              // v1, v2, v3
__device__ int   g_flag;               // monotonic build-done counter

// ---------------------------------------------------------------------------
// f32x2 packed helpers
// ---------------------------------------------------------------------------
__device__ __forceinline__ unsigned long long pack2(float lo, float hi) {
    unsigned long long r;
    asm("mov.b64 %0, {%1, %2};" : "=l"(r) : "f"(lo), "f"(hi));
    return r;
}
__device__ __forceinline__ void unpack2(unsigned long long v, float& lo, float& hi) {
    asm("mov.b64 {%0, %1}, %2;" : "=f"(lo), "=f"(hi) : "l"(v));
}
__device__ __forceinline__ void ffma2(unsigned long long& d, unsigned long long a,
                                      unsigned long long b) {
    asm("fma.rn.f32x2 %0, %1, %2, %0;" : "+l"(d) : "l"(a), "l"(b));
}
__device__ __forceinline__ unsigned long long add2(unsigned long long a,
                                                   unsigned long long b) {
    unsigned long long r;
    asm("add.rn.f32x2 %0, %1, %2;" : "=l"(r) : "l"(a), "l"(b));
    return r;
}

// ---------------------------------------------------------------------------
// Fused kernel. One block per batch element.
// Blocks 0..7 additionally build W channel oc=blockIdx (block 0 also Vt/vk).
// smem overlay: build buffers reuse the Wp/scm/sc1s region (disjoint in time).
// ---------------------------------------------------------------------------
__global__ __launch_bounds__(TPB, 7) void fused_kernel(const float* __restrict__ x,
                                                       const float* __restrict__ lpm,
                                                       const float* __restrict__ pm,
                                                       const float* __restrict__ stdv,
                                                       const float* __restrict__ w0,
                                                       const float* __restrict__ ws,
                                                       float* __restrict__ out) {
    __shared__ __align__(16) unsigned char ov[22528];
    __shared__ float Vt[A_DIM * 21];
    __shared__ int   sav[L_DIM];
    __shared__ int   sWmax[4];
    __shared__ float sw0s[CH * 3];

    // main-phase views of the overlay
    unsigned long long* Wp   = (unsigned long long*)ov;             // 16 KB [j*512+l]
    unsigned long long* scm  = (unsigned long long*)(ov + 16384);   // 4 KB  (c2<<32)|c3
    unsigned*           sc1s = (unsigned*)(ov + 20480);             // 2 KB  c1 | (s<<24)

    int tid = threadIdx.x, b = blockIdx.x;
    int warp = tid >> 5, lane = tid & 31;

    // --- Phase A: decode one-hot via weighted-sum FMA (LDG burst first) ---
    const float* xb = x + (size_t)b * (L_DIM * A_DIM);
    int lmax = -1;
    #pragma unroll
    for (int r = 0; r < 4; r++) {
        int l = tid + r * TPB;
        const float4* p = (const float4*)(xb + l * A_DIM);
        float4 q0 = p[0], q1 = p[1], q2 = p[2], q3 = p[3], q4 = p[4];
        float a0 = fmaf(q0.x, 1.f, fmaf(q0.y, 2.f, fmaf(q0.z, 3.f, q0.w * 4.f)));
        float a1 = fmaf(q1.x, 5.f, fmaf(q1.y, 6.f, fmaf(q1.z, 7.f, q1.w * 8.f)));
        float a2 = fmaf(q2.x, 9.f, fmaf(q2.y, 10.f, fmaf(q2.z, 11.f, q2.w * 12.f)));
        float a3 = fmaf(q3.x, 13.f, fmaf(q3.y, 14.f, fmaf(q3.z, 15.f, q3.w * 16.f)));
        float a4 = fmaf(q4.x, 17.f, fmaf(q4.y, 18.f, fmaf(q4.z, 19.f, q4.w * 20.f)));
        float fa = ((a0 + a1) + (a2 + a3)) + a4;
        int v = (int)fa;                  // exact: small ints
        sav[l] = (v == 0) ? 20 : v - 1;
        if (v != 0) lmax = l;
    }
    lmax = __reduce_max_sync(0xFFFFFFFFu, lmax);
    if (lane == 0) sWmax[warp] = lmax;

    // --- W builder (blocks 0..7): adjoint composition into g_Wf ---
    if (b < CH) {
        if (b == 0) {
            for (int i = tid; i < A_DIM * 21; i += TPB) {
                int a = i / 21, s = i % 21;
                float v = (s == a) ? 1.f : 0.f;
                if (s < A_DIM) {
                    if (a > s && a <= A_DIM - 2)
                        v += fminf(fmaxf(lpm[s * A_DIM + a], 0.001f), 1.f) * pm[s * A_DIM + a];
                    if (a < s)
                        v += fminf(fmaxf(lpm[a * A_DIM + s], 0.001f), 1.f) * pm[a * A_DIM + s];
                }
                g_Vt[i] = v;
            }
            if (tid < 3) {
                float s0 = stdv[0];
                float k = (float)(tid + 1);
                g_vk[tid] = expf(-(k * k) / (2.f * s0 * s0));
            }
        }
        // overlay build views (free until Wp/scm/sc1s are used)
        float* buf0 = (float*)ov;             // stride 256, 8 KB
        float* buf1 = (float*)(ov + 8192);    // stride 128, 4 KB
        float* sws  = (float*)(ov + 12288);   // 1536 floats, 6 KB

        for (int i = tid; i < 8 * CH * CH * 3; i += TPB) sws[i] = ws[i];
        if (tid < CH * 3) sw0s[tid] = w0[tid];
        if (tid < CH) buf0[tid * 256] = (tid == b) ? 1.f : 0.f;
        __syncthreads();

        float* cur = buf0; int curs = 256;
        for (int j = 7; j >= 0; j--) {
            int sh = 8 - j;                    // L2h = 1 << sh
            int L2h = 1 << sh;
            float* dst = (j & 1) ? buf1 : buf0;
            int dsts = (j & 1) ? 128 : 256;
            const float* w = sws + j * (CH * CH * 3);
            for (int e = tid; e < CH * L2h; e += TPB) {
                int ci = e >> sh, q = e & (L2h - 1);
                float acc = 0.f;
                #pragma unroll
                for (int co = 0; co < CH; co++) {
                    const float* wc = w + (co * CH + ci) * 3;
                    #pragma unroll
                    for (int t = 0; t < 3; t++) {
                        int p = q + 1 - t;
                        if (p >= 0 && p < L2h) acc += wc[t] * 0.5f * cur[co * curs + (p >> 1)];
                    }
                }
                dst[ci * dsts + q] = acc;
            }
            __syncthreads();
            cur = dst; curs = dsts;
        }
        // final backward through pool0+conv0: cur = buf0 (CH x 256)
        float* gw = g_Wf + (b >> 1) * (L_DIM * 2) + (b & 1);
        for (int q = tid; q < 512; q += TPB) {
            float acc = 0.f;
            #pragma unroll
            for (int co = 0; co < CH; co++) {
                #pragma unroll
                for (int t = 0; t < 3; t++) {
                    int p = q + 1 - t;
                    if (p >= 0 && p < 512) acc += sw0s[co * 3 + t] * 0.5f * cur[co * 256 + (p >> 1)];
                }
            }
            gw[2 * q] = acc;
        }
        __threadfence();
        __syncthreads();
        if (tid == 0) atomicAdd(&g_flag, 1);
    }
    __syncthreads();   // sav/sWmax ready; builders done with overlay

    int Lmax = max(max(sWmax[0], sWmax[1]), max(sWmax[2], sWmax[3]));
    int NB = min(L_DIM, (Lmax + 4 + 31) & ~31);   // positions >= NB contribute 0

    // --- Phase B: exclusive class masks (independent of W -> before spin) ---
    for (int l = tid; l < NB; l += TPB) {
        unsigned c1, c2, c3;
        if (l == 0) {
            c3 = (1u << sav[0]) | (1u << sav[1]) | (1u << sav[2]) | (1u << sav[3]);
            c2 = 0u; c1 = 0u;
        } else if (l == L_DIM - 1) {
            c3 = (1u << sav[511]) | (1u << sav[510]) | (1u << sav[509]) | (1u << sav[508]);
            c2 = 0u; c1 = 0u;
        } else {
            unsigned m1 = (1u << sav[l - 1]) | (1u << sav[l + 1]);
            unsigned m2 = ((l >= 2) ? (1u << sav[l - 2]) : 0u) |
                          ((l <= 509) ? (1u << sav[l + 2]) : 0u);
            unsigned m3 = ((l >= 3) ? (1u << sav[l - 3]) : 0u) |
                          ((l <= 508) ? (1u << sav[l + 3]) : 0u);
            c3 = m3;
            c2 = m2 & ~m3;
            c1 = m1 & ~(m2 | m3);
        }
        scm[l]  = ((unsigned long long)c2 << 32) | c3;
        sc1s[l] = (c1 & 0x1FFFFFu) | ((unsigned)sav[l] << 24);
    }

    // --- rendezvous: wait until all 8 W channels (+Vt/vk) are published ---
    if (tid == 0) {
        while (atomicAdd(&g_flag, 0) < CH) __nanosleep(64);
    }
    __syncthreads();
    __threadfence();   // acquire: order subsequent g_Wf/g_Vt reads

    // --- copy block-invariant tables (straight vector copies) ---
    {
        const float4* srcW = (const float4*)g_Wf;
        float4* dstW = (float4*)Wp;
        #pragma unroll
        for (int r = 0; r < 8; r++) dstW[tid + r * TPB] = srcW[tid + r * TPB];
        const float4* srcV = (const float4*)g_Vt;   // 420 floats = 105 float4
        float4* dstV = (float4*)Vt;
        if (tid < 105) dstV[tid] = srcV[tid];
    }
    float v1 = g_vk[0], v2 = g_vk[1], v3 = g_vk[2];
    __syncthreads();

    int abase = warp * 5;
    unsigned long long acc[5][4];
    #pragma unroll
    for (int aa = 0; aa < 5; aa++)
        #pragma unroll
        for (int j = 0; j < 4; j++) acc[aa][j] = 0ull;

    unsigned abit[5]; int vb[5];
    #pragma unroll
    for (int aa = 0; aa < 5; aa++) {
        abit[aa] = 1u << (abase + aa);
        vb[aa] = (abase + aa) * 21;
    }

    // --- Phase C: bounded, barrier-free packed accumulation (conflict-free LDS.64) ---
    int NI = NB >> 5;
    #pragma unroll 2
    for (int i = 0; i < NI; i++) {
        int l = lane + 32 * i;
        unsigned long long m = scm[l];
        unsigned c3m = (unsigned)m;
        unsigned c2m = (unsigned)(m >> 32);
        unsigned t = sc1s[l];
        unsigned c1m = t & 0x1FFFFFu;
        int s = (int)(t >> 24);
        unsigned long long w0p = Wp[l];
        unsigned long long w1p = Wp[512 + l];
        unsigned long long w2p = Wp[1024 + l];
        unsigned long long w3p = Wp[1536 + l];
        #pragma unroll
        for (int aa = 0; aa < 5; aa++) {
            float rv = (c3m & abit[aa]) ? v3
                     : (c2m & abit[aa]) ? v2
                     : (c1m & abit[aa]) ? v1 : 0.f;
            float h = rv + Vt[vb[aa] + s];
            unsigned long long hh = pack2(h, h);
            ffma2(acc[aa][0], w0p, hh);
            ffma2(acc[aa][1], w1p, hh);
            ffma2(acc[aa][2], w2p, hh);
            ffma2(acc[aa][3], w3p, hh);
        }
    }

    // --- Phase D: native u64 butterfly (2 SHFL + 1 FADD2 per step) ---
    #pragma unroll
    for (int aa = 0; aa < 5; aa++) {
        #pragma unroll
        for (int j = 0; j < 4; j++) {
            unsigned long long v = acc[aa][j];
            #pragma unroll
            for (int off = 16; off; off >>= 1)
                v = add2(v, __shfl_xor_sync(0xFFFFFFFFu, v, off));
            acc[aa][j] = v;
        }
        if (lane == 0) {
            float r[8];
            #pragma unroll
            for (int j = 0; j < 4; j++) unpack2(acc[aa][j], r[2 * j], r[2 * j + 1]);
            float4* o = (float4*)(out + (size_t)b * (A_DIM * CH) + (abase + aa) * CH);
            o[0] = make_float4(r[0], r[1], r[2], r[3]);
            o[1] = make_float4(r[4], r[5], r[6], r[7]);
        }
    }
}

// ---------------------------------------------------------------------------
// Inputs (metadata order): x, masks(unused), lpm, pm, std, w0, ws
// Output: float32 (B, A, CH) = (1024, 20, 8)
// ---------------------------------------------------------------------------
extern "C" void kernel_launch(void* const* d_in, const int* in_sizes, int n_in,
                              void* d_out, int out_size) {
    const float* x    = (const float*)d_in[0];
    const float* lpm  = (const float*)d_in[2];
    const float* pm   = (const float*)d_in[3];
    const float* stdv = (const float*)d_in[4];
    const float* w0   = (const float*)d_in[5];
    const float* ws   = (const float*)d_in[6];
    float* out = (float*)d_out;

    fused_kernel<<<B_DIM, TPB>>>(x, lpm, pm, stdv, w0, ws, out);
}

// round 16
// speedup vs baseline: 1.0667x; 1.0105x over previous
#include <cuda_runtime.h>
#include <math.h>

#define A_DIM 20
#define L_DIM 512
#define CH 8
#define B_DIM 1024
#define TPB 128   // 4 warps; warp w owns amino acids 5w..5w+4

__device__ float g_Wf[4 * L_DIM * 2];  // interleaved channel pairs: [j*1024 + 2l + parity]
__device__ float g_Vt[A_DIM * 21];     // Vt[a*21+s] = V[s][a] + (s==a); s=20 -> 0
__device__ float g_vk[3];              // v1, v2, v3
__device__ int   g_flag;               // monotonic build-done counter

// ---------------------------------------------------------------------------
// f32x2 packed helpers
// ---------------------------------------------------------------------------
__device__ __forceinline__ unsigned long long pack2(float lo, float hi) {
    unsigned long long r;
    asm("mov.b64 %0, {%1, %2};" : "=l"(r) : "f"(lo), "f"(hi));
    return r;
}
__device__ __forceinline__ void unpack2(unsigned long long v, float& lo, float& hi) {
    asm("mov.b64 {%0, %1}, %2;" : "=f"(lo), "=f"(hi) : "l"(v));
}
__device__ __forceinline__ void ffma2(unsigned long long& d, unsigned long long a,
                                      unsigned long long b) {
    asm("fma.rn.f32x2 %0, %1, %2, %0;" : "+l"(d) : "l"(a), "l"(b));
}
__device__ __forceinline__ unsigned long long add2(unsigned long long a,
                                                   unsigned long long b) {
    unsigned long long r;
    asm("add.rn.f32x2 %0, %1, %2;" : "=l"(r) : "l"(a), "l"(b));
    return r;
}
__device__ __forceinline__ int ld_acquire_gpu(const int* p) {
    int v;
    asm volatile("ld.acquire.gpu.global.b32 %0, [%1];" : "=r"(v) : "l"(p) : "memory");
    return v;
}
__device__ __forceinline__ void red_release_add(int* p, int v) {
    asm volatile("red.release.gpu.global.add.s32 [%0], %1;" :: "l"(p), "r"(v) : "memory");
}

// ---------------------------------------------------------------------------
// Fused kernel. One block per batch element.
// Blocks 0..7 additionally build W channel oc=blockIdx (block 0 also Vt/vk).
// smem overlay: build buffers reuse the Wp/scm/sc1s region (disjoint in time).
// ---------------------------------------------------------------------------
__global__ __launch_bounds__(TPB, 7) void fused_kernel(const float* __restrict__ x,
                                                       const float* __restrict__ lpm,
                                                       const float* __restrict__ pm,
                                                       const float* __restrict__ stdv,
                                                       const float* __restrict__ w0,
                                                       const float* __restrict__ ws,
                                                       float* __restrict__ out) {
    __shared__ __align__(16) unsigned char ov[22528];
    __shared__ float Vt[A_DIM * 21];
    __shared__ int   sav[L_DIM];
    __shared__ int   sWmax[4];
    __shared__ float sw0s[CH * 3];

    // main-phase views of the overlay
    unsigned long long* Wp   = (unsigned long long*)ov;             // 16 KB [j*512+l]
    unsigned long long* scm  = (unsigned long long*)(ov + 16384);   // 4 KB  (c2<<32)|c3
    unsigned*           sc1s = (unsigned*)(ov + 20480);             // 2 KB  c1 | (s<<24)

    int tid = threadIdx.x, b = blockIdx.x;
    int warp = tid >> 5, lane = tid & 31;

    // --- Phase A: decode one-hot via weighted-sum FMA (LDG burst first) ---
    const float* xb = x + (size_t)b * (L_DIM * A_DIM);
    int lmax = -1;
    #pragma unroll
    for (int r = 0; r < 4; r++) {
        int l = tid + r * TPB;
        const float4* p = (const float4*)(xb + l * A_DIM);
        float4 q0 = p[0], q1 = p[1], q2 = p[2], q3 = p[3], q4 = p[4];
        float a0 = fmaf(q0.x, 1.f, fmaf(q0.y, 2.f, fmaf(q0.z, 3.f, q0.w * 4.f)));
        float a1 = fmaf(q1.x, 5.f, fmaf(q1.y, 6.f, fmaf(q1.z, 7.f, q1.w * 8.f)));
        float a2 = fmaf(q2.x, 9.f, fmaf(q2.y, 10.f, fmaf(q2.z, 11.f, q2.w * 12.f)));
        float a3 = fmaf(q3.x, 13.f, fmaf(q3.y, 14.f, fmaf(q3.z, 15.f, q3.w * 16.f)));
        float a4 = fmaf(q4.x, 17.f, fmaf(q4.y, 18.f, fmaf(q4.z, 19.f, q4.w * 20.f)));
        float fa = ((a0 + a1) + (a2 + a3)) + a4;
        int v = (int)fa;                  // exact: small ints
        sav[l] = (v == 0) ? 20 : v - 1;
        if (v != 0) lmax = l;
    }
    lmax = __reduce_max_sync(0xFFFFFFFFu, lmax);
    if (lane == 0) sWmax[warp] = lmax;

    // --- W builder (blocks 0..7): adjoint composition into g_Wf ---
    if (b < CH) {
        if (b == 0) {
            for (int i = tid; i < A_DIM * 21; i += TPB) {
                int a = i / 21, s = i % 21;
                float v = (s == a) ? 1.f : 0.f;
                if (s < A_DIM) {
                    if (a > s && a <= A_DIM - 2)
                        v += fminf(fmaxf(lpm[s * A_DIM + a], 0.001f), 1.f) * pm[s * A_DIM + a];
                    if (a < s)
                        v += fminf(fmaxf(lpm[a * A_DIM + s], 0.001f), 1.f) * pm[a * A_DIM + s];
                }
                g_Vt[i] = v;
            }
            if (tid < 3) {
                float s0 = stdv[0];
                float k = (float)(tid + 1);
                g_vk[tid] = expf(-(k * k) / (2.f * s0 * s0));
            }
        }
        // overlay build views (free until Wp/scm/sc1s are used)
        float* buf0 = (float*)ov;             // stride 256, 8 KB
        float* buf1 = (float*)(ov + 8192);    // stride 128, 4 KB
        float* sws  = (float*)(ov + 12288);   // 1536 floats, 6 KB

        for (int i = tid; i < 8 * CH * CH * 3; i += TPB) sws[i] = ws[i];
        if (tid < CH * 3) sw0s[tid] = w0[tid];
        if (tid < CH) buf0[tid * 256] = (tid == b) ? 1.f : 0.f;
        __syncthreads();

        float* cur = buf0; int curs = 256;
        for (int j = 7; j >= 0; j--) {
            int sh = 8 - j;                    // L2h = 1 << sh
            int L2h = 1 << sh;
            float* dst = (j & 1) ? buf1 : buf0;
            int dsts = (j & 1) ? 128 : 256;
            const float* w = sws + j * (CH * CH * 3);
            for (int e = tid; e < CH * L2h; e += TPB) {
                int ci = e >> sh, q = e & (L2h - 1);
                float acc = 0.f;
                #pragma unroll
                for (int co = 0; co < CH; co++) {
                    const float* wc = w + (co * CH + ci) * 3;
                    #pragma unroll
                    for (int t = 0; t < 3; t++) {
                        int p = q + 1 - t;
                        if (p >= 0 && p < L2h) acc += wc[t] * 0.5f * cur[co * curs + (p >> 1)];
                    }
                }
                dst[ci * dsts + q] = acc;
            }
            __syncthreads();
            cur = dst; curs = dsts;
        }
        // final backward through pool0+conv0: cur = buf0 (CH x 256)
        float* gw = g_Wf + (b >> 1) * (L_DIM * 2) + (b & 1);
        for (int q = tid; q < 512; q += TPB) {
            float acc = 0.f;
            #pragma unroll
            for (int co = 0; co < CH; co++) {
                #pragma unroll
                for (int t = 0; t < 3; t++) {
                    int p = q + 1 - t;
                    if (p >= 0 && p < 512) acc += sw0s[co * 3 + t] * 0.5f * cur[co * 256 + (p >> 1)];
                }
            }
            gw[2 * q] = acc;
        }
        __threadfence();
        __syncthreads();
        if (tid == 0) red_release_add(&g_flag, 1);
    }
    __syncthreads();   // sav/sWmax ready; builders done with overlay

    int Lmax = max(max(sWmax[0], sWmax[1]), max(sWmax[2], sWmax[3]));
    int NB = min(L_DIM, (Lmax + 4 + 31) & ~31);   // positions >= NB contribute 0

    // --- Phase B: exclusive class masks (independent of W -> before wait) ---
    for (int l = tid; l < NB; l += TPB) {
        unsigned c1, c2, c3;
        if (l == 0) {
            c3 = (1u << sav[0]) | (1u << sav[1]) | (1u << sav[2]) | (1u << sav[3]);
            c2 = 0u; c1 = 0u;
        } else if (l == L_DIM - 1) {
            c3 = (1u << sav[511]) | (1u << sav[510]) | (1u << sav[509]) | (1u << sav[508]);
            c2 = 0u; c1 = 0u;
        } else {
            unsigned m1 = (1u << sav[l - 1]) | (1u << sav[l + 1]);
            unsigned m2 = ((l >= 2) ? (1u << sav[l - 2]) : 0u) |
                          ((l <= 509) ? (1u << sav[l + 2]) : 0u);
            unsigned m3 = ((l >= 3) ? (1u << sav[l - 3]) : 0u) |
                          ((l <= 508) ? (1u << sav[l + 3]) : 0u);
            c3 = m3;
            c2 = m2 & ~m3;
            c1 = m1 & ~(m2 | m3);
        }
        scm[l]  = ((unsigned long long)c2 << 32) | c3;
        sc1s[l] = (c1 & 0x1FFFFFu) | ((unsigned)sav[l] << 24);
    }

    // --- rendezvous: acquire-load spin (no atomic-ALU serialization) ---
    if (tid == 0) {
        while (ld_acquire_gpu(&g_flag) < CH) __nanosleep(64);
    }
    __syncthreads();

    // --- copy block-invariant tables (straight vector copies) ---
    {
        const float4* srcW = (const float4*)g_Wf;
        float4* dstW = (float4*)Wp;
        #pragma unroll
        for (int r = 0; r < 8; r++) dstW[tid + r * TPB] = srcW[tid + r * TPB];
        const float4* srcV = (const float4*)g_Vt;   // 420 floats = 105 float4
        float4* dstV = (float4*)Vt;
        if (tid < 105) dstV[tid] = srcV[tid];
    }
    float v1 = g_vk[0], v2 = g_vk[1], v3 = g_vk[2];
    __syncthreads();

    int abase = warp * 5;
    unsigned long long acc[5][4];
    #pragma unroll
    for (int aa = 0; aa < 5; aa++)
        #pragma unroll
        for (int j = 0; j < 4; j++) acc[aa][j] = 0ull;

    unsigned abit[5]; int vb[5];
    #pragma unroll
    for (int aa = 0; aa < 5; aa++) {
        abit[aa] = 1u << (abase + aa);
        vb[aa] = (abase + aa) * 21;
    }

    // --- Phase C: bounded, barrier-free packed accumulation (conflict-free LDS.64) ---
    int NI = NB >> 5;
    #pragma unroll 2
    for (int i = 0; i < NI; i++) {
        int l = lane + 32 * i;
        unsigned long long m = scm[l];
        unsigned c3m = (unsigned)m;
        unsigned c2m = (unsigned)(m >> 32);
        unsigned t = sc1s[l];
        unsigned c1m = t & 0x1FFFFFu;
        int s = (int)(t >> 24);
        unsigned long long w0p = Wp[l];
        unsigned long long w1p = Wp[512 + l];
        unsigned long long w2p = Wp[1024 + l];
        unsigned long long w3p = Wp[1536 + l];
        #pragma unroll
        for (int aa = 0; aa < 5; aa++) {
            float rv = (c3m & abit[aa]) ? v3
                     : (c2m & abit[aa]) ? v2
                     : (c1m & abit[aa]) ? v1 : 0.f;
            float h = rv + Vt[vb[aa] + s];
            unsigned long long hh = pack2(h, h);
            ffma2(acc[aa][0], w0p, hh);
            ffma2(acc[aa][1], w1p, hh);
            ffma2(acc[aa][2], w2p, hh);
            ffma2(acc[aa][3], w3p, hh);
        }
    }

    // --- Phase D: native u64 butterfly (2 SHFL + 1 FADD2 per step) ---
    #pragma unroll
    for (int aa = 0; aa < 5; aa++) {
        #pragma unroll
        for (int j = 0; j < 4; j++) {
            unsigned long long v = acc[aa][j];
            #pragma unroll
            for (int off = 16; off; off >>= 1)
                v = add2(v, __shfl_xor_sync(0xFFFFFFFFu, v, off));
            acc[aa][j] = v;
        }
        if (lane == 0) {
            float r[8];
            #pragma unroll
            for (int j = 0; j < 4; j++) unpack2(acc[aa][j], r[2 * j], r[2 * j + 1]);
            float4* o = (float4*)(out + (size_t)b * (A_DIM * CH) + (abase + aa) * CH);
            o[0] = make_float4(r[0], r[1], r[2], r[3]);
            o[1] = make_float4(r[4], r[5], r[6], r[7]);
        }
    }
}

// ---------------------------------------------------------------------------
// Inputs (metadata order): x, masks(unused), lpm, pm, std, w0, ws
// Output: float32 (B, A, CH) = (1024, 20, 8)
// ---------------------------------------------------------------------------
extern "C" void kernel_launch(void* const* d_in, const int* in_sizes, int n_in,
                              void* d_out, int out_size) {
    const float* x    = (const float*)d_in[0];
    const float* lpm  = (const float*)d_in[2];
    const float* pm   = (const float*)d_in[3];
    const float* stdv = (const float*)d_in[4];
    const float* w0   = (const float*)d_in[5];
    const float* ws   = (const float*)d_in[6];
    float* out = (float*)d_out;

    fused_kernel<<<B_DIM, TPB>>>(x, lpm, pm, stdv, w0, ws, out);
}